// round 8
// baseline (speedup 1.0000x reference)
#include <cuda_runtime.h>
#include <math.h>

// Problem constants
#define NN 16384
#define NB 64
#define NVOCAB 100
#define NL0 128
#define NH 64

// Scratch (__device__ globals — no allocation allowed)
__device__ float g_px[NN], g_py[NN], g_pz[NN], g_sq[NN];
__device__ int2  g_band[NN];          // (lo, hi) packed: one 8B load per thread
__device__ float g_table[NVOCAB];

// ---------------------------------------------------------------------------
// Kernel A: fused prep + MLP table.
//   blocks [0, 64):    prep — SoA pos split, sq, same-batch band via binary
//                      search on sorted batch (int32/int64 auto-detected).
//   blocks [64, 164):  MLP collapsed to 100-entry vocab table.
// ---------------------------------------------------------------------------
__global__ void fused_prep_mlp(const void* __restrict__ batch_raw,
                               const float* __restrict__ pos,
                               const float* __restrict__ emb,
                               const float* __restrict__ w1,
                               const float* __restrict__ b1,
                               const float* __restrict__ w2,
                               const float* __restrict__ b2) {
    if (blockIdx.x < 64) {
        // ---- prep ----
        int i = blockIdx.x * 256 + threadIdx.x;

        float x = pos[3 * i + 0];
        float y = pos[3 * i + 1];
        float z = pos[3 * i + 2];
        g_px[i] = x; g_py[i] = y; g_pz[i] = z;
        // sq: separate rounds, no fma contraction (matches XLA mul+add)
        g_sq[i] = __fadd_rn(__fadd_rn(__fmul_rn(x, x), __fmul_rn(y, y)),
                            __fmul_rn(z, z));

        // Detect batch dtype: int32 layout -> word [NN-1] = max batch (~63);
        // int64 LE layout -> word [NN-1] is a high word = 0.
        const int* w32 = (const int*)batch_raw;
        bool is32 = (w32[NN - 1] != 0);

        long long bi = is32 ? (long long)w32[i]
                            : ((const long long*)batch_raw)[i];

        // lower_bound
        int lo = 0, hi = NN;
        while (lo < hi) {
            int m = (lo + hi) >> 1;
            long long bm = is32 ? (long long)w32[m]
                                : ((const long long*)batch_raw)[m];
            if (bm < bi) lo = m + 1; else hi = m;
        }
        int lb = lo;
        // upper_bound
        lo = 0; hi = NN;
        while (lo < hi) {
            int m = (lo + hi) >> 1;
            long long bm = is32 ? (long long)w32[m]
                                : ((const long long*)batch_raw)[m];
            if (bm <= bi) lo = m + 1; else hi = m;
        }
        g_band[i] = make_int2(lb, lo);
    } else {
        // ---- MLP table: out depends on z only through emb[z]; 100 rows ----
        __shared__ float sh[NH];
        int v = blockIdx.x - 64;
        int j = threadIdx.x;

        if (j < NH) {
            const float* e = emb + (size_t)v * NL0;
            float acc = b1[j];
#pragma unroll 8
            for (int k = 0; k < NL0; k++)
                acc = fmaf(e[k], w1[k * NH + j], acc);
            // silu(x) = x * sigmoid(x)
            float s = 1.0f / (1.0f + expf(-acc));
            sh[j] = (acc * s) * w2[j];
        }
        __syncthreads();
        if (j == 0) {
            float o = 0.0f;
            for (int k = 0; k < NH; k++) o += sh[k];
            g_table[v] = o + b2[0];
        }
    }
}

// ---------------------------------------------------------------------------
// Kernel B: adjacency mask (HBM-write bound) + gather epilogue.
//   blocks [0, 64) additionally write out[i] = table[z[i]] first (table was
//   produced by kernel A; ordered by the kernel boundary).
// Grid-stride over NN*NN/4 float4 chunks (exactly 8 iterations per thread);
// out-of-band chunks store zeros with no pos loads. In-band:
//   d2 = (sq_i + sq_j) - 2*dot   (dot = ascending fma chain)
// exactly matching the reference's sq[:,None]+sq[None,:]-2*(pos@pos.T).
// PLAIN stores: __stcs measurably reduced DRAM throughput on this stream
// (72.5% vs 76.4% of peak) — default write-back with full-line coalescing
// is the fast path for a write-once 1 GB output.
// ---------------------------------------------------------------------------
#define TOTAL4 (NN * (NN / 4))  // 67,108,864 float4 chunks

__global__ void adj_gather_kernel(const int* __restrict__ z,
                                  float* __restrict__ out,
                                  float4* __restrict__ adj) {
    if (blockIdx.x < 64) {
        int i = blockIdx.x * 256 + threadIdx.x;
        out[i] = g_table[z[i]];
    }

    unsigned stride = gridDim.x * blockDim.x;
    for (unsigned t = blockIdx.x * blockDim.x + threadIdx.x;
         t < (unsigned)TOTAL4; t += stride) {
        int i  = (int)(t >> 12);            // NN/4 = 4096 chunks per row
        int j0 = (int)((t & 4095u) << 2);
        int2 band = g_band[i];
        int lo = band.x, hi = band.y;

        float4 v = make_float4(0.f, 0.f, 0.f, 0.f);
        if (j0 + 3 >= lo && j0 < hi) {
            float xi = g_px[i], yi = g_py[i], zi = g_pz[i], sqi = g_sq[i];
            float r[4];
#pragma unroll
            for (int k = 0; k < 4; k++) {
                int j = j0 + k;
                float val = 0.0f;
                if (j >= lo && j < hi && j != i) {
                    float dot = fmaf(zi, g_pz[j],
                                fmaf(yi, g_py[j],
                                     __fmul_rn(xi, g_px[j])));
                    float d2 = __fsub_rn(__fadd_rn(sqi, g_sq[j]),
                                         __fmul_rn(2.0f, dot));
                    val = (d2 < 64.0f) ? 1.0f : 0.0f;
                }
                r[k] = val;
            }
            v = make_float4(r[0], r[1], r[2], r[3]);
        }
        adj[t] = v;
    }
}

// ---------------------------------------------------------------------------
extern "C" void kernel_launch(void* const* d_in, const int* in_sizes, int n_in,
                              void* d_out, int out_size) {
    const int*   z     = (const int*)d_in[0];
    const void*  batch = d_in[1];           // int32 or int64, device-detected
    const float* pos   = (const float*)d_in[2];
    const float* emb   = (const float*)d_in[3];
    const float* w1    = (const float*)d_in[4];
    const float* b1    = (const float*)d_in[5];
    const float* w2    = (const float*)d_in[6];
    const float* b2    = (const float*)d_in[7];
    float* out = (float*)d_out;

    fused_prep_mlp<<<164, 256>>>(batch, pos, emb, w1, b1, w2, b2);
    adj_gather_kernel<<<32768, 256>>>(z, out, (float4*)(out + NN));
}

// round 9
// speedup vs baseline: 1.1962x; 1.1962x over previous
#include <cuda_runtime.h>
#include <math.h>

// Problem constants
#define NN 16384
#define NB 64
#define NVOCAB 100
#define NL0 128
#define NH 64

// Scratch (__device__ globals — no allocation allowed)
__device__ float g_px[NN], g_py[NN], g_pz[NN], g_sq[NN];
__device__ int2  g_band[NN];          // (lo, hi) packed: one 8B load per thread
__device__ float g_table[NVOCAB];

// ---------------------------------------------------------------------------
// Kernel A: fused prep + MLP table.
//   blocks [0, 64):    prep — SoA pos split, sq, same-batch band via binary
//                      search on sorted batch (int32/int64 auto-detected).
//   blocks [64, 164):  MLP collapsed to 100-entry vocab table.
// ---------------------------------------------------------------------------
__global__ void fused_prep_mlp(const void* __restrict__ batch_raw,
                               const float* __restrict__ pos,
                               const float* __restrict__ emb,
                               const float* __restrict__ w1,
                               const float* __restrict__ b1,
                               const float* __restrict__ w2,
                               const float* __restrict__ b2) {
    if (blockIdx.x < 64) {
        // ---- prep ----
        int i = blockIdx.x * 256 + threadIdx.x;

        float x = pos[3 * i + 0];
        float y = pos[3 * i + 1];
        float z = pos[3 * i + 2];
        g_px[i] = x; g_py[i] = y; g_pz[i] = z;
        // sq: separate rounds, no fma contraction (matches XLA mul+add)
        g_sq[i] = __fadd_rn(__fadd_rn(__fmul_rn(x, x), __fmul_rn(y, y)),
                            __fmul_rn(z, z));

        // Detect batch dtype: int32 layout -> word [NN-1] = max batch (~63);
        // int64 LE layout -> word [NN-1] is a high word = 0.
        const int* w32 = (const int*)batch_raw;
        bool is32 = (w32[NN - 1] != 0);

        long long bi = is32 ? (long long)w32[i]
                            : ((const long long*)batch_raw)[i];

        // lower_bound
        int lo = 0, hi = NN;
        while (lo < hi) {
            int m = (lo + hi) >> 1;
            long long bm = is32 ? (long long)w32[m]
                                : ((const long long*)batch_raw)[m];
            if (bm < bi) lo = m + 1; else hi = m;
        }
        int lb = lo;
        // upper_bound
        lo = 0; hi = NN;
        while (lo < hi) {
            int m = (lo + hi) >> 1;
            long long bm = is32 ? (long long)w32[m]
                                : ((const long long*)batch_raw)[m];
            if (bm <= bi) lo = m + 1; else hi = m;
        }
        g_band[i] = make_int2(lb, lo);
    } else {
        // ---- MLP table: out depends on z only through emb[z]; 100 rows ----
        __shared__ float sh[NH];
        int v = blockIdx.x - 64;
        int j = threadIdx.x;

        if (j < NH) {
            const float* e = emb + (size_t)v * NL0;
            float acc = b1[j];
#pragma unroll 8
            for (int k = 0; k < NL0; k++)
                acc = fmaf(e[k], w1[k * NH + j], acc);
            // silu(x) = x * sigmoid(x)
            float s = 1.0f / (1.0f + expf(-acc));
            sh[j] = (acc * s) * w2[j];
        }
        __syncthreads();
        if (j == 0) {
            float o = 0.0f;
            for (int k = 0; k < NH; k++) o += sh[k];
            g_table[v] = o + b2[0];
        }
    }
}

// ---------------------------------------------------------------------------
// Kernel B: adjacency mask (HBM-write bound) + gather epilogue.
//   blocks [0, 64) additionally write out[i] = table[z[i]] first.
//
// Mapping: block b -> row (b >> 1), half (b & 1). Each block covers 2048
// float4 chunks (half a row); thread handles chunks tid + k*256, k=0..7
// (lane-contiguous per store instruction -> full coalescing). Row state
// (band, pos_i, sq_i) is hoisted; blocks with no band overlap take a pure
// 8x STG zero loop with zero per-iteration ALU.
//
// __stcs (evict-first streaming) is MANDATORY here: A/B'd at wall-clock,
// plain stores cost +26us (180.8 vs 154.3). ncu single-pass DRAM% said the
// opposite — do not trust it over graph-replay wall time for this kernel.
//
// In-band: d2 = (sq_i + sq_j) - 2*dot (ascending fma chain) — exact match
// of the reference's sq[:,None]+sq[None,:]-2*(pos@pos.T) rounding.
// ---------------------------------------------------------------------------
__global__ void adj_gather_kernel(const int* __restrict__ z,
                                  float* __restrict__ out,
                                  float4* __restrict__ adj) {
    if (blockIdx.x < 64) {
        int idx = blockIdx.x * 256 + threadIdx.x;
        out[idx] = g_table[z[idx]];
    }

    int row  = blockIdx.x >> 1;
    int half = blockIdx.x & 1;
    int2 band = g_band[row];
    int lo = band.x, hi = band.y;

    unsigned cbase = (unsigned)row * 4096u + (unsigned)half * 2048u; // chunk base
    int jbase = half * 8192;                                        // element base

    const float4 zero = make_float4(0.f, 0.f, 0.f, 0.f);

    // No overlap between this half-row [jbase, jbase+8192) and [lo, hi)?
    if (jbase + 8192 <= lo || jbase >= hi) {
        // Pure zero-fill fast path (~98% of blocks)
#pragma unroll
        for (int k = 0; k < 8; k++)
            __stcs(&adj[cbase + threadIdx.x + k * 256], zero);
    } else {
        float xi = g_px[row], yi = g_py[row], zi = g_pz[row], sqi = g_sq[row];
#pragma unroll
        for (int k = 0; k < 8; k++) {
            int c  = threadIdx.x + k * 256;      // chunk within half-row
            int j0 = jbase + (c << 2);           // first element of chunk
            float4 v = zero;
            if (j0 + 3 >= lo && j0 < hi) {
                float r[4];
#pragma unroll
                for (int e = 0; e < 4; e++) {
                    int j = j0 + e;
                    float val = 0.0f;
                    if (j >= lo && j < hi && j != row) {
                        float dot = fmaf(zi, g_pz[j],
                                    fmaf(yi, g_py[j],
                                         __fmul_rn(xi, g_px[j])));
                        float d2 = __fsub_rn(__fadd_rn(sqi, g_sq[j]),
                                             __fmul_rn(2.0f, dot));
                        val = (d2 < 64.0f) ? 1.0f : 0.0f;
                    }
                    r[e] = val;
                }
                v = make_float4(r[0], r[1], r[2], r[3]);
            }
            __stcs(&adj[cbase + c], v);
        }
    }
}

// ---------------------------------------------------------------------------
extern "C" void kernel_launch(void* const* d_in, const int* in_sizes, int n_in,
                              void* d_out, int out_size) {
    const int*   z     = (const int*)d_in[0];
    const void*  batch = d_in[1];           // int32 or int64, device-detected
    const float* pos   = (const float*)d_in[2];
    const float* emb   = (const float*)d_in[3];
    const float* w1    = (const float*)d_in[4];
    const float* b1    = (const float*)d_in[5];
    const float* w2    = (const float*)d_in[6];
    const float* b2    = (const float*)d_in[7];
    float* out = (float*)d_out;

    fused_prep_mlp<<<164, 256>>>(batch, pos, emb, w1, b1, w2, b2);
    adj_gather_kernel<<<32768, 256>>>(z, out, (float4*)(out + NN));
}